// round 13
// baseline (speedup 1.0000x reference)
#include <cuda_runtime.h>

// DCN cross network, collapsed algebra, warp-per-2-rows (barrier-free).
//   xi_{l+1} = x0*(xi_l . w_l) + b_l + xi_l
//   xi_l = a_l*x0 + sum_{m<l} b_m   (bias coefficients provably stay 1)
//   s_l = a_l*(x0.w_l) + sum_{m<l}(b_m.w_l);  a_{l+1} = a_l + s_l;  a_0 = 1
//   out = a_4*x0 + sum_m b_m
// Each WARP owns TWO rows: weight chunks are loaded once and used for both
// rows (halves weight L1 traffic, doubles independent work per warp).
// One shuffle-reduction pass covers all 8 dots. No smem, no __syncthreads.

constexpr int D = 1024;
constexpr int THREADS = 256;           // 8 warps per CTA
constexpr int ROWS_PER_WARP = 2;
constexpr int CHUNKS = D / 128;        // 8 float4 per lane per row

__device__ float  g_k[3];              // {c01, c02+c12, c03+c13+c23}
__device__ float4 g_bsum4[D / 4];      // b0+b1+b2+b3 packed float4

__global__ __launch_bounds__(1024) void precompute_kernel(
    const float* __restrict__ w, const float* __restrict__ b)
{
    const int e = threadIdx.x;         // 0..1023
    const int lane = e & 31, warp = e >> 5;

    float w1 = w[D + e], w2 = w[2 * D + e], w3 = w[3 * D + e];
    float b0 = b[e], b1 = b[D + e], b2 = b[2 * D + e], b3 = b[3 * D + e];

    reinterpret_cast<float*>(g_bsum4)[e] = (b0 + b1) + (b2 + b3);

    // k0 = b0.w1 ; k1 = (b0+b1).w2 ; k2 = (b0+b1+b2).w3
    float p0 = b0 * w1;
    float p1 = (b0 + b1) * w2;
    float p2 = ((b0 + b1) + b2) * w3;

    __shared__ float red[32][3];
#pragma unroll
    for (int o = 16; o > 0; o >>= 1) {
        p0 += __shfl_xor_sync(0xffffffffu, p0, o);
        p1 += __shfl_xor_sync(0xffffffffu, p1, o);
        p2 += __shfl_xor_sync(0xffffffffu, p2, o);
    }
    if (lane == 0) { red[warp][0] = p0; red[warp][1] = p1; red[warp][2] = p2; }
    __syncthreads();

    if (warp == 0 && lane < 3) {
        float v = 0.f;
#pragma unroll
        for (int i = 0; i < 32; i++) v += red[i][lane];
        g_k[lane] = v;
    }
}

__global__ __launch_bounds__(THREADS, 4) void cross_network_kernel(
    const float* __restrict__ x, const float* __restrict__ w,
    float* __restrict__ out, int batch)
{
    const int lane = threadIdx.x & 31;
    const int gwarp = blockIdx.x * (THREADS / 32) + (threadIdx.x >> 5);
    const int rowA = gwarp * ROWS_PER_WARP;
    if (rowA >= batch) return;
    const int rowB = (rowA + 1 < batch) ? rowA + 1 : rowA;  // safe tail clamp

    const float4* __restrict__ xA = reinterpret_cast<const float4*>(x) +
                                    (size_t)rowA * (D / 4);
    const float4* __restrict__ xB = reinterpret_cast<const float4*>(x) +
                                    (size_t)rowB * (D / 4);
    const float4* __restrict__ w4 = reinterpret_cast<const float4*>(w);
    float4* __restrict__ oA = reinterpret_cast<float4*>(out) +
                              (size_t)rowA * (D / 4);
    float4* __restrict__ oB = reinterpret_cast<float4*>(out) +
                              (size_t)rowB * (D / 4);

    // Partial dots for all 4 layers x 2 rows. Weights loaded ONCE per chunk.
    float4 pA = make_float4(0.f, 0.f, 0.f, 0.f);
    float4 pB = make_float4(0.f, 0.f, 0.f, 0.f);
#pragma unroll
    for (int j = 0; j < CHUNKS; j++) {
        const int eoff = j * 32 + lane;
        float4 xa = xA[eoff];
        float4 xb = xB[eoff];
        float4 w0 = w4[0 * (D / 4) + eoff];
        float4 w1 = w4[1 * (D / 4) + eoff];
        float4 w2 = w4[2 * (D / 4) + eoff];
        float4 w3 = w4[3 * (D / 4) + eoff];

        pA.x = fmaf(xa.x, w0.x, pA.x); pA.x = fmaf(xa.y, w0.y, pA.x);
        pA.x = fmaf(xa.z, w0.z, pA.x); pA.x = fmaf(xa.w, w0.w, pA.x);
        pB.x = fmaf(xb.x, w0.x, pB.x); pB.x = fmaf(xb.y, w0.y, pB.x);
        pB.x = fmaf(xb.z, w0.z, pB.x); pB.x = fmaf(xb.w, w0.w, pB.x);

        pA.y = fmaf(xa.x, w1.x, pA.y); pA.y = fmaf(xa.y, w1.y, pA.y);
        pA.y = fmaf(xa.z, w1.z, pA.y); pA.y = fmaf(xa.w, w1.w, pA.y);
        pB.y = fmaf(xb.x, w1.x, pB.y); pB.y = fmaf(xb.y, w1.y, pB.y);
        pB.y = fmaf(xb.z, w1.z, pB.y); pB.y = fmaf(xb.w, w1.w, pB.y);

        pA.z = fmaf(xa.x, w2.x, pA.z); pA.z = fmaf(xa.y, w2.y, pA.z);
        pA.z = fmaf(xa.z, w2.z, pA.z); pA.z = fmaf(xa.w, w2.w, pA.z);
        pB.z = fmaf(xb.x, w2.x, pB.z); pB.z = fmaf(xb.y, w2.y, pB.z);
        pB.z = fmaf(xb.z, w2.z, pB.z); pB.z = fmaf(xb.w, w2.w, pB.z);

        pA.w = fmaf(xa.x, w3.x, pA.w); pA.w = fmaf(xa.y, w3.y, pA.w);
        pA.w = fmaf(xa.z, w3.z, pA.w); pA.w = fmaf(xa.w, w3.w, pA.w);
        pB.w = fmaf(xb.x, w3.x, pB.w); pB.w = fmaf(xb.y, w3.y, pB.w);
        pB.w = fmaf(xb.z, w3.z, pB.w); pB.w = fmaf(xb.w, w3.w, pB.w);
    }

    // One warp-shuffle reduction pass for all 8 dots.
#pragma unroll
    for (int o = 16; o > 0; o >>= 1) {
        pA.x += __shfl_xor_sync(0xffffffffu, pA.x, o);
        pA.y += __shfl_xor_sync(0xffffffffu, pA.y, o);
        pA.z += __shfl_xor_sync(0xffffffffu, pA.z, o);
        pA.w += __shfl_xor_sync(0xffffffffu, pA.w, o);
        pB.x += __shfl_xor_sync(0xffffffffu, pB.x, o);
        pB.y += __shfl_xor_sync(0xffffffffu, pB.y, o);
        pB.z += __shfl_xor_sync(0xffffffffu, pB.z, o);
        pB.w += __shfl_xor_sync(0xffffffffu, pB.w, o);
    }

    // Scalar recurrences (uniform across warp).
    const float c01 = g_k[0], k2 = g_k[1], k3 = g_k[2];

    float aA = 1.f + pA.x;
    float sA = fmaf(aA, pA.y, c01);  aA += sA;
    sA = fmaf(aA, pA.z, k2);         aA += sA;
    sA = fmaf(aA, pA.w, k3);         aA += sA;

    float aB = 1.f + pB.x;
    float sB = fmaf(aB, pB.y, c01);  aB += sB;
    sB = fmaf(aB, pB.z, k2);         aB += sB;
    sB = fmaf(aB, pB.w, k3);         aB += sB;

    // Epilogue: out = a * x0 + bsum. x re-loaded (L1-hot); streaming stores.
#pragma unroll
    for (int j = 0; j < CHUNKS; j++) {
        const int eoff = j * 32 + lane;
        float4 bsv = g_bsum4[eoff];
        float4 xa = xA[eoff];
        float4 xb = xB[eoff];
        float4 ov;
        ov.x = fmaf(aA, xa.x, bsv.x);
        ov.y = fmaf(aA, xa.y, bsv.y);
        ov.z = fmaf(aA, xa.z, bsv.z);
        ov.w = fmaf(aA, xa.w, bsv.w);
        __stcs(&oA[eoff], ov);
        ov.x = fmaf(aB, xb.x, bsv.x);
        ov.y = fmaf(aB, xb.y, bsv.y);
        ov.z = fmaf(aB, xb.z, bsv.z);
        ov.w = fmaf(aB, xb.w, bsv.w);
        __stcs(&oB[eoff], ov);
    }
}

extern "C" void kernel_launch(void* const* d_in, const int* in_sizes, int n_in,
                              void* d_out, int out_size)
{
    const float* x = (const float*)d_in[0];
    const float* w = (const float*)d_in[1];
    const float* b = (const float*)d_in[2];
    float* out = (float*)d_out;

    const int batch = in_sizes[0] / D;                       // 16384
    const int rows_per_cta = (THREADS / 32) * ROWS_PER_WARP; // 16
    const int grid = (batch + rows_per_cta - 1) / rows_per_cta;

    precompute_kernel<<<1, 1024>>>(w, b);
    cross_network_kernel<<<grid, THREADS>>>(x, w, out, batch);
}

// round 14
// speedup vs baseline: 1.1311x; 1.1311x over previous
#include <cuda_runtime.h>
#include <cstdint>

// DCN cross network, collapsed algebra, warp-per-row, cp.async-staged x.
//   xi_{l+1} = x0*(xi_l . w_l) + b_l + xi_l
//   xi_l = a_l*x0 + sum_{m<l} b_m   (bias coefficients provably stay 1)
//   s_l = a_l*(x0.w_l) + sum_{m<l}(b_m.w_l);  a_{l+1} = a_l + s_l;  a_0 = 1
//   out = a_4*x0 + sum_m b_m
// Each warp owns one row. The row's 4 KB of x is brought in with 8
// cp.async.cg per lane (full row in flight, ZERO register cost, L1 bypass),
// then consumed from the warp's private smem slot. Each lane reads only the
// smem bytes it copied itself -> cp.async.wait_group is the only sync needed.

constexpr int D = 1024;
constexpr int THREADS = 256;           // 8 warps per CTA
constexpr int WARPS = THREADS / 32;
constexpr int CHUNKS = D / 128;        // 8 float4 per lane per row

__device__ float  g_k[3];              // {c01, c02+c12, c03+c13+c23}
__device__ float4 g_bsum4[D / 4];      // b0+b1+b2+b3 packed float4

__global__ __launch_bounds__(1024) void precompute_kernel(
    const float* __restrict__ w, const float* __restrict__ b)
{
    const int e = threadIdx.x;         // 0..1023
    const int lane = e & 31, warp = e >> 5;

    float w1 = w[D + e], w2 = w[2 * D + e], w3 = w[3 * D + e];
    float b0 = b[e], b1 = b[D + e], b2 = b[2 * D + e], b3 = b[3 * D + e];

    reinterpret_cast<float*>(g_bsum4)[e] = (b0 + b1) + (b2 + b3);

    // k0 = b0.w1 ; k1 = (b0+b1).w2 ; k2 = (b0+b1+b2).w3
    float p0 = b0 * w1;
    float p1 = (b0 + b1) * w2;
    float p2 = ((b0 + b1) + b2) * w3;

    __shared__ float red[32][3];
#pragma unroll
    for (int o = 16; o > 0; o >>= 1) {
        p0 += __shfl_xor_sync(0xffffffffu, p0, o);
        p1 += __shfl_xor_sync(0xffffffffu, p1, o);
        p2 += __shfl_xor_sync(0xffffffffu, p2, o);
    }
    if (lane == 0) { red[warp][0] = p0; red[warp][1] = p1; red[warp][2] = p2; }
    __syncthreads();

    if (warp == 0 && lane < 3) {
        float v = 0.f;
#pragma unroll
        for (int i = 0; i < 32; i++) v += red[i][lane];
        g_k[lane] = v;
    }
}

__device__ __forceinline__ uint32_t smem_u32(const void* p) {
    uint32_t a;
    asm("{ .reg .u64 t; cvta.to.shared.u64 t, %1; cvt.u32.u64 %0, t; }"
        : "=r"(a) : "l"(p));
    return a;
}

__global__ __launch_bounds__(THREADS) void cross_network_kernel(
    const float* __restrict__ x, const float* __restrict__ w,
    float* __restrict__ out, int batch)
{
    __shared__ float4 xtile[WARPS][D / 4];   // 8 warps x 4 KB = 32 KB

    const int lane = threadIdx.x & 31;
    const int warp = threadIdx.x >> 5;
    const int row = blockIdx.x * WARPS + warp;
    if (row >= batch) return;

    const float4* __restrict__ xrow = reinterpret_cast<const float4*>(x) +
                                      (size_t)row * (D / 4);
    const float4* __restrict__ w4 = reinterpret_cast<const float4*>(w);
    float4* __restrict__ orow = reinterpret_cast<float4*>(out) +
                                (size_t)row * (D / 4);

    // Stage full x row into this warp's smem slot. 8 x 16B cp.async per lane:
    // full row in flight with no register cost; .cg bypasses L1.
    const uint32_t sbase = smem_u32(&xtile[warp][0]);
#pragma unroll
    for (int j = 0; j < CHUNKS; j++) {
        const int eoff = j * 32 + lane;
        asm volatile("cp.async.cg.shared.global [%0], [%1], 16;"
                     :: "r"(sbase + eoff * 16), "l"(xrow + eoff));
    }
    asm volatile("cp.async.commit_group;");

    // Uniform scalars (L2-hot broadcast) fetched while x is in flight.
    const float c01 = g_k[0], k2 = g_k[1], k3 = g_k[2];

    asm volatile("cp.async.wait_group 0;" ::: "memory");

    // Partial dots for all 4 layers; x from smem (29-cyc LDS), weights L1-hot.
    float4 p = make_float4(0.f, 0.f, 0.f, 0.f);
#pragma unroll
    for (int j = 0; j < CHUNKS; j++) {
        const int eoff = j * 32 + lane;
        float4 xv = xtile[warp][eoff];
        float4 w0 = w4[0 * (D / 4) + eoff];
        float4 w1 = w4[1 * (D / 4) + eoff];
        float4 w2 = w4[2 * (D / 4) + eoff];
        float4 w3 = w4[3 * (D / 4) + eoff];
        p.x = fmaf(xv.x, w0.x, p.x); p.x = fmaf(xv.y, w0.y, p.x);
        p.x = fmaf(xv.z, w0.z, p.x); p.x = fmaf(xv.w, w0.w, p.x);
        p.y = fmaf(xv.x, w1.x, p.y); p.y = fmaf(xv.y, w1.y, p.y);
        p.y = fmaf(xv.z, w1.z, p.y); p.y = fmaf(xv.w, w1.w, p.y);
        p.z = fmaf(xv.x, w2.x, p.z); p.z = fmaf(xv.y, w2.y, p.z);
        p.z = fmaf(xv.z, w2.z, p.z); p.z = fmaf(xv.w, w2.w, p.z);
        p.w = fmaf(xv.x, w3.x, p.w); p.w = fmaf(xv.y, w3.y, p.w);
        p.w = fmaf(xv.z, w3.z, p.w); p.w = fmaf(xv.w, w3.w, p.w);
    }

    // One warp-shuffle reduction pass for all 4 dots. No barriers anywhere.
#pragma unroll
    for (int o = 16; o > 0; o >>= 1) {
        p.x += __shfl_xor_sync(0xffffffffu, p.x, o);
        p.y += __shfl_xor_sync(0xffffffffu, p.y, o);
        p.z += __shfl_xor_sync(0xffffffffu, p.z, o);
        p.w += __shfl_xor_sync(0xffffffffu, p.w, o);
    }

    // Scalar recurrence (uniform across warp).
    float a = 1.f + p.x;                       // layer 0
    float s = fmaf(a, p.y, c01);  a += s;      // layer 1
    s = fmaf(a, p.z, k2);         a += s;      // layer 2
    s = fmaf(a, p.w, k3);         a += s;      // layer 3

    // Epilogue: out = a * x0 + bsum. x from smem (this lane's own bytes).
#pragma unroll
    for (int j = 0; j < CHUNKS; j++) {
        const int eoff = j * 32 + lane;
        float4 xv = xtile[warp][eoff];
        float4 bsv = g_bsum4[eoff];
        float4 ov;
        ov.x = fmaf(a, xv.x, bsv.x);
        ov.y = fmaf(a, xv.y, bsv.y);
        ov.z = fmaf(a, xv.z, bsv.z);
        ov.w = fmaf(a, xv.w, bsv.w);
        orow[eoff] = ov;
    }
}

extern "C" void kernel_launch(void* const* d_in, const int* in_sizes, int n_in,
                              void* d_out, int out_size)
{
    const float* x = (const float*)d_in[0];
    const float* w = (const float*)d_in[1];
    const float* b = (const float*)d_in[2];
    float* out = (float*)d_out;

    const int batch = in_sizes[0] / D;                 // 16384
    const int grid = (batch + WARPS - 1) / WARPS;      // 2048

    precompute_kernel<<<1, 1024>>>(w, b);
    cross_network_kernel<<<grid, THREADS>>>(x, w, out, batch);
}